// round 10
// baseline (speedup 1.0000x reference)
#include <cuda_runtime.h>
#include <cuda_bf16.h>
#include <cuda_fp16.h>
#include <math.h>

#define DV 33
#define D2 (DV*DV)        // 1089
#define D3 (DV*DV*DV)     // 35937
#define B 4
#define NPIX (1024*1024)

// ---------------- scratch ----------------------------------------------------
// feature maps stored DE-INTERLEAVED: per (b,c) plane of HW*HW floats is split
// into even columns [0, HW*HW/2) then odd columns [HW*HW/2, HW*HW)
__device__ float g_resized[B*3*256*256];
__device__ float g_x1[B*16*128*128];
__device__ float g_x2[B*32*64*64];
__device__ float g_x3[B*64*32*32];
__device__ float g_x4[B*128*16*16];
__device__ float g_codes[B*512];
// raw stats per (b,c): [sum,sumsq]: ss1@0(128) ss2@128(256) ss3@384(512) ss4@896(1024)
__device__ float g_stats[1920];
__device__ float g_wts[B*3];
__device__ float g_verts[B*3*DV];
// cube-packed LUT: per (b,i,j,k) one 32B record =
//   [f32 min][f32 scale][24 x u8 q], q idx = 3*(di*4+dj*2+dk)+ch
__device__ uint4 g_lutC[B*D3*2];

// ---------------- resize (+ stats zeroing): 1024->256, de-interleaved out ----
__global__ void resize_k(const float* __restrict__ lq, float* __restrict__ out,
                         float* __restrict__ stats)
{
    int idx = blockIdx.x * blockDim.x + threadIdx.x;
    if (idx < 1920) stats[idx] = 0.f;
    if (idx >= B*3*256*256) return;
    int ox = idx & 255;
    int oy = (idx >> 8) & 255;
    int bc = idx >> 16;
    const float* ip = lq + (size_t)bc * 1024 * 1024 + (size_t)(4*oy+1)*1024 + (4*ox+1);
    float v = 0.25f * (ip[0] + ip[1] + ip[1024] + ip[1025]);
    out[(size_t)bc*65536 + (ox & 1)*32768 + oy*128 + (ox >> 1)] = v;
}

// ---------------- direct conv: k3 s2 p1 + LeakyReLU; de-interleaved I/O ------
template<int IC, int OC, int OCB, int INHW, int OUTHW, bool HAS_IN>
__global__ void __launch_bounds__(256) conv_k(
                       const float* __restrict__ in, const float* __restrict__ w,
                       const float* __restrict__ bias,
                       const float* __restrict__ stat_in,
                       const float* __restrict__ gamma, const float* __restrict__ beta,
                       float* __restrict__ stat_out,
                       float* __restrict__ out)
{
    const int HW2 = INHW/2;
    const int HALF = INHW*INHW/2;
    const int OHALF = OUTHW*OUTHW/2;
    const int b = blockIdx.z;
    const int ocg = blockIdx.y;
    const int tid = threadIdx.x;
    __shared__ float sw[IC*9*OCB];
    __shared__ float ssc[IC];
    __shared__ float ssh[IC];
    for (int i = tid; i < IC*9*OCB; i += 256) {
        int o = i % OCB, t = i / OCB;
        int k = t % 9, ic = t / 9;
        sw[i] = w[((ocg*OCB + o)*IC + ic)*9 + k];
    }
    if (HAS_IN) {
        for (int i = tid; i < IC; i += 256) {
            const float invn = 1.f / (float)(INHW*INHW);
            float s1 = stat_in[(b*IC+i)*2], s2 = stat_in[(b*IC+i)*2+1];
            float mean = s1 * invn;
            float var  = s2 * invn - mean*mean;
            float sc = gamma[i] * rsqrtf(var + 1e-5f);
            ssc[i] = sc;
            ssh[i] = beta[i] - mean * sc;
        }
    }
    __syncthreads();

    int p = blockIdx.x*256 + tid;         // OUTHW*OUTHW multiple of 256
    int oy = p / OUTHW, ox = p % OUTHW;
    float acc[OCB];
    #pragma unroll
    for (int o = 0; o < OCB; o++) acc[o] = bias[ocg*OCB+o];

    const bool okT = (oy > 0);
    const bool okL = (ox > 0);
    const float* inb = in + (size_t)b*IC*INHW*INHW + (2*oy-1)*HW2 + ox;

    for (int ic = 0; ic < IC; ic++) {
        const float* ipE = inb + (size_t)ic*INHW*INHW;
        const float* ipO = ipE + HALF;
        float v[9];
        #pragma unroll
        for (int ky = 0; ky < 3; ky++) {
            bool okR = (okT || ky > 0);
            int off = ky*HW2;
            v[ky*3+0] = (okR && okL) ? ipO[off-1] : 0.f;
            v[ky*3+1] = okR          ? ipE[off]   : 0.f;
            v[ky*3+2] = okR          ? ipO[off]   : 0.f;
        }
        if (HAS_IN) {
            float s = ssc[ic], sh = ssh[ic];
            #pragma unroll
            for (int ky = 0; ky < 3; ky++) {
                bool okR = (okT || ky > 0);
                v[ky*3+0] = (okR && okL) ? fmaf(v[ky*3+0], s, sh) : 0.f;
                v[ky*3+1] = okR          ? fmaf(v[ky*3+1], s, sh) : 0.f;
                v[ky*3+2] = okR          ? fmaf(v[ky*3+2], s, sh) : 0.f;
            }
        }
        #pragma unroll
        for (int k = 0; k < 9; k++) {
            float t = v[k];
            #pragma unroll
            for (int o = 0; o < OCB; o++)
                acc[o] = fmaf(t, sw[(ic*9+k)*OCB+o], acc[o]);
        }
    }

    const size_t oaddr = (ox & 1)*OHALF + oy*(OUTHW/2) + (ox >> 1);
    float ys[OCB];
    #pragma unroll
    for (int o = 0; o < OCB; o++) {
        float y = acc[o];
        y = y >= 0.f ? y : 0.2f*y;
        ys[o] = y;
        out[((size_t)b*OC + ocg*OCB + o)*OUTHW*OUTHW + oaddr] = y;
    }

    float s1[OCB], s2[OCB];
    #pragma unroll
    for (int o = 0; o < OCB; o++) { s1[o] = ys[o]; s2[o] = ys[o]*ys[o]; }
    #pragma unroll
    for (int o = 0; o < OCB; o++) {
        #pragma unroll
        for (int off = 16; off; off >>= 1) {
            s1[o] += __shfl_xor_sync(0xffffffffu, s1[o], off);
            s2[o] += __shfl_xor_sync(0xffffffffu, s2[o], off);
        }
    }
    __shared__ float2 red[OCB][8];
    int warp = tid >> 5, lane = tid & 31;
    if (lane == 0) {
        #pragma unroll
        for (int o = 0; o < OCB; o++) red[o][warp] = make_float2(s1[o], s2[o]);
    }
    __syncthreads();
    if (tid < OCB) {
        float a = 0.f, c = 0.f;
        #pragma unroll
        for (int wdx = 0; wdx < 8; wdx++) { a += red[tid][wdx].x; c += red[tid][wdx].y; }
        int bc = b*OC + ocg*OCB + tid;
        atomicAdd(stat_out + bc*2, a);
        atomicAdd(stat_out + bc*2+1, c);
    }
}

// ---------------- conv5 + LeakyReLU + avgpool(2) -> codes (de-interleaved in)
// grid (32, B): 32 oc-groups of 4; 256 thr = 64 px x 4 osub (1 oc each)
__global__ void __launch_bounds__(256) conv5_pool_k(
                             const float* __restrict__ in, const float* __restrict__ w,
                             const float* __restrict__ bias,
                             const float* __restrict__ stat_in,
                             const float* __restrict__ gamma, const float* __restrict__ beta,
                             float* __restrict__ codes)
{
    const int IC = 128, OCPB = 4;
    const int b = blockIdx.y, ocg = blockIdx.x;
    const int tid = threadIdx.x;
    const int px = tid & 63, osub = tid >> 6;
    const int oy = px >> 3, ox = px & 7;

    __shared__ float sw[IC*9*OCPB];
    __shared__ float ssc[IC], ssh[IC];
    __shared__ float sred[OCPB][64];

    for (int i = tid; i < IC; i += 256) {
        const float invn = 1.f / 256.f;
        float s1 = stat_in[(b*IC+i)*2], s2 = stat_in[(b*IC+i)*2+1];
        float mean = s1 * invn;
        float var  = s2 * invn - mean*mean;
        float sc = gamma[i] * rsqrtf(var + 1e-5f);
        ssc[i] = sc;
        ssh[i] = beta[i] - mean * sc;
    }
    for (int i = tid; i < IC*9*OCPB; i += 256) {
        int o = i % OCPB, t = i / OCPB;
        int k = t % 9, ic = t / 9;
        sw[i] = w[((ocg*OCPB + o)*IC + ic)*9 + k];
    }
    __syncthreads();

    float acc = bias[ocg*OCPB + osub];

    const bool okT = (oy > 0), okL = (ox > 0);
    const float* inb = in + (size_t)b*IC*256 + (2*oy-1)*8 + ox;

    for (int ic = 0; ic < IC; ic++) {
        const float* ipE = inb + ic*256;
        const float* ipO = ipE + 128;
        float s = ssc[ic], sh = ssh[ic];
        float v[9];
        #pragma unroll
        for (int ky = 0; ky < 3; ky++) {
            bool okR = (okT || ky > 0);
            int off = ky*8;
            float l = (okR && okL) ? ipO[off-1] : 0.f;
            float m = okR          ? ipE[off]   : 0.f;
            float r = okR          ? ipO[off]   : 0.f;
            v[ky*3+0] = (okR && okL) ? fmaf(l, s, sh) : 0.f;
            v[ky*3+1] = okR          ? fmaf(m, s, sh) : 0.f;
            v[ky*3+2] = okR          ? fmaf(r, s, sh) : 0.f;
        }
        #pragma unroll
        for (int k = 0; k < 9; k++)
            acc = fmaf(v[k], sw[(ic*9+k)*OCPB + osub], acc);
    }

    sred[osub][px] = acc >= 0.f ? acc : 0.2f*acc;
    __syncthreads();
    if (tid < 16) {
        int o = tid >> 2, q = tid & 3, py = q >> 1, qx = q & 1;
        float s = 0.f;
        #pragma unroll
        for (int yy = 0; yy < 4; yy++)
            #pragma unroll
            for (int xx = 0; xx < 4; xx++)
                s += sred[o][(py*4+yy)*8 + (qx*4+xx)];
        codes[b*512 + (ocg*OCPB + o)*4 + q] = s * (1.f/16.f);
    }
}

// ---------------- LUT weights + AdaInt vertices (warp-per-row GEMV) ----------
__global__ void mlp_k(const float* __restrict__ codes,
                      const float* __restrict__ lw, const float* __restrict__ lb,
                      const float* __restrict__ aw, const float* __restrict__ ab,
                      float* __restrict__ wts, float* __restrict__ verts,
                      float* __restrict__ out_w, float* __restrict__ out_v)
{
    int b = blockIdx.x;
    __shared__ float sc[512];
    __shared__ float pre[96];
    int t = threadIdx.x;
    int warp = t >> 5, lane = t & 31;
    for (int i = t; i < 512; i += 256) sc[i] = codes[b*512 + i];
    __syncthreads();

    // 99 rows: 0..95 -> aw (pre), 96..98 -> lw (wts)
    for (int r = warp; r < 99; r += 8) {
        const float* row = (r < 96) ? (aw + (size_t)r*512) : (lw + (size_t)(r-96)*512);
        float acc = 0.f;
        #pragma unroll
        for (int k = 0; k < 16; k++)
            acc = fmaf(sc[lane + k*32], row[lane + k*32], acc);
        #pragma unroll
        for (int off = 16; off; off >>= 1)
            acc += __shfl_xor_sync(0xffffffffu, acc, off);
        if (lane == 0) {
            if (r < 96) pre[r] = acc + ab[r];
            else {
                float v = acc + lb[r-96];
                wts[b*3 + (r-96)] = v;
                out_w[b*3 + (r-96)] = v;
            }
        }
    }
    __syncthreads();

    if (warp < 3) {
        float x = pre[warp*32 + lane];
        float m = x;
        #pragma unroll
        for (int off = 16; off; off >>= 1) m = fmaxf(m, __shfl_xor_sync(0xffffffffu, m, off));
        float e = expf(x - m);
        float ssum = e;
        #pragma unroll
        for (int off = 16; off; off >>= 1) ssum += __shfl_xor_sync(0xffffffffu, ssum, off);
        float p = e / ssum;
        float cs = p;
        #pragma unroll
        for (int off = 1; off < 32; off <<= 1) {
            float v = __shfl_up_sync(0xffffffffu, cs, off);
            if (lane >= off) cs += v;
        }
        float* vp = verts + (b*3 + warp)*DV;
        float* vo = out_v + (b*3 + warp)*DV;
        if (lane == 0) { vp[0] = 0.f; vo[0] = 0.f; }
        vp[lane+1] = cs;
        vo[lane+1] = cs;
    }
}

// ---------------- lut synthesis into cube-packed u8 records ------------------
__global__ void lutC_k(const float* __restrict__ bw, const float* __restrict__ wts,
                       uint4* __restrict__ lutC)
{
    int i = blockIdx.x*blockDim.x + threadIdx.x;
    if (i >= B*D3) return;
    int b = i / D3, s = i - b*D3;
    int k = s % DV;
    int j = (s / DV) % DV;
    int ii = s / D2;
    int di = (ii < DV-1) ? D2 : 0;
    int dj = (j  < DV-1) ? DV : 0;
    int dk = (k  < DV-1) ? 1  : 0;
    float w0 = wts[b*3], w1 = wts[b*3+1], w2 = wts[b*3+2];

    float vals[24];
    #pragma unroll
    for (int a = 0; a < 2; a++)
        #pragma unroll
        for (int c = 0; c < 2; c++)
            #pragma unroll
            for (int d = 0; d < 2; d++) {
                int idx = s + a*di + c*dj + d*dk;
                int corner = a*4 + c*2 + d;
                #pragma unroll
                for (int ch = 0; ch < 3; ch++) {
                    const float* p = bw + ((size_t)ch*D3 + idx)*3;
                    vals[corner*3 + ch] = fmaf(w0, p[0], fmaf(w1, p[1], w2*p[2]));
                }
            }

    float mn = vals[0], mx = vals[0];
    #pragma unroll
    for (int t = 1; t < 24; t++) { mn = fminf(mn, vals[t]); mx = fmaxf(mx, vals[t]); }
    float scale = (mx - mn) * (1.f/255.f);
    float inv = (scale > 0.f) ? 1.f/scale : 0.f;

    unsigned int u[6];
    #pragma unroll
    for (int wd = 0; wd < 6; wd++) {
        unsigned int r = 0;
        #pragma unroll
        for (int bb = 0; bb < 4; bb++) {
            int t = wd*4 + bb;
            int q = __float2int_rn((vals[t] - mn) * inv);
            q = min(max(q, 0), 255);
            r |= ((unsigned int)q) << (8*bb);
        }
        u[wd] = r;
    }
    uint4 lo, hi;
    lo.x = __float_as_uint(mn);
    lo.y = __float_as_uint(scale);
    lo.z = u[0]; lo.w = u[1];
    hi.x = u[2]; hi.y = u[3]; hi.z = u[4]; hi.w = u[5];
    lutC[(size_t)i*2]   = lo;
    lutC[(size_t)i*2+1] = hi;
}

// ---------------- AiLUT transform: record-table searchsorted + cube trilerp --
__global__ void __launch_bounds__(256) transform_k(
                            const float* __restrict__ lq, const uint4* __restrict__ lutC,
                            const float* __restrict__ verts, float* __restrict__ out)
{
    int b = blockIdx.x >> 10;
    int blk = blockIdx.x & 1023;
    int tid = threadIdx.x;
    __shared__ float sv[3][DV];
    __shared__ float4 s_int[3][33];    // per-interval: (vlo, inv, basef, vhi)
    __shared__ float4 s_edge[3][128];  // per 1/128-bin: record of left-edge interval
    if (tid < 99) sv[tid/33][tid%33] = verts[b*99 + tid];
    __syncthreads();
    // build interval records (intervals 1..32)
    if (tid < 96) {
        int ch = tid / 32, idx = (tid & 31) + 1;
        float vlo = sv[ch][idx-1], vhi = sv[ch][idx];
        float4 r;
        r.x = vlo;
        r.y = 1.f / (vhi - vlo + 1e-8f);
        r.z = (float)(idx - 1);
        r.w = (idx == 32) ? __int_as_float(0x7f800000) : vhi;  // +inf guard on last
        s_int[ch][idx] = r;
    }
    __syncthreads();
    // build edge table
    for (int t = tid; t < 384; t += 256) {
        int ch = t >> 7, e = t & 127;
        float edge = (float)e * (1.f/128.f);
        int idx = 0;
        #pragma unroll 8
        for (int m = 1; m <= 32; m++)
            if (sv[ch][m] <= edge) idx = m;
        s_edge[ch][e] = s_int[ch][min(idx, 31) + 1];
    }
    __syncthreads();

    int n = (blk*256 + tid) * 4;
    const float* lqb = lq + (size_t)b*3*NPIX;
    float4 R  = *(const float4*)(lqb + n);
    float4 G  = *(const float4*)(lqb + NPIX + n);
    float4 Bl = *(const float4*)(lqb + 2*NPIX + n);

    float xr[4] = {R.x, R.y, R.z, R.w};
    float xg[4] = {G.x, G.y, G.z, G.w};
    float xb[4] = {Bl.x, Bl.y, Bl.z, Bl.w};
    float orr[4], org[4], orb[4];

    const uint4* base = lutC + (size_t)b*D3*2;

    #pragma unroll
    for (int px = 0; px < 4; px++) {
        int i0, j0, k0;
        float fr, fg, fb;
        float xs[3] = {xr[px], xg[px], xb[px]};
        #pragma unroll
        for (int ch = 0; ch < 3; ch++) {
            float x = xs[ch];
            int e = min((int)(x * 128.f), 127);
            float4 rec = s_edge[ch][e];
            while (x > rec.w)
                rec = s_int[ch][(int)rec.z + 2];
            float f = fminf((x - rec.x) * rec.y, 1.f);
            int cb = (int)rec.z;
            if (ch == 0) { i0 = cb; fr = f; }
            else if (ch == 1) { j0 = cb; fg = f; }
            else { k0 = cb; fb = f; }
        }

        size_t e0 = (size_t)(i0*D2 + j0*DV + k0)*2;
        uint4 lo4 = base[e0];
        uint4 hi4 = base[e0+1];
        float mn = __uint_as_float(lo4.x);
        float sc = __uint_as_float(lo4.y);
        unsigned int u[6] = {lo4.z, lo4.w, hi4.x, hi4.y, hi4.z, hi4.w};

        #pragma unroll
        for (int ch = 0; ch < 3; ch++) {
            float q[8];
            #pragma unroll
            for (int corner = 0; corner < 8; corner++) {
                int t = corner*3 + ch;
                q[corner] = (float)((u[t >> 2] >> ((t & 3)*8)) & 0xffu);
            }
            // corner = di*4 + dj*2 + dk
            float l00 = fmaf(fb, q[1] - q[0], q[0]);
            float l01 = fmaf(fb, q[3] - q[2], q[2]);
            float l10 = fmaf(fb, q[5] - q[4], q[4]);
            float l11 = fmaf(fb, q[7] - q[6], q[6]);
            float h0  = fmaf(fg, l01 - l00, l00);
            float h1  = fmaf(fg, l11 - l10, l10);
            float vq  = fmaf(fr, h1 - h0, h0);
            float v   = fmaf(sc, vq, mn);
            v = fminf(fmaxf(v, 0.f), 1.f);
            if (ch == 0) orr[px] = v; else if (ch == 1) org[px] = v; else orb[px] = v;
        }
    }

    float* ob = out + (size_t)b*3*NPIX + n;
    *(float4*)(ob)          = make_float4(orr[0], orr[1], orr[2], orr[3]);
    *(float4*)(ob + NPIX)   = make_float4(org[0], org[1], org[2], org[3]);
    *(float4*)(ob + 2*NPIX) = make_float4(orb[0], orb[1], orb[2], orb[3]);
}

// ---------------- host launcher ----------------------------------------------
extern "C" void kernel_launch(void* const* d_in, const int* in_sizes, int n_in,
                              void* d_out, int out_size)
{
    const float* lq  = (const float*)d_in[0];
    const float* w1  = (const float*)d_in[1];
    const float* b1  = (const float*)d_in[2];
    const float* g1  = (const float*)d_in[3];
    const float* be1 = (const float*)d_in[4];
    const float* w2  = (const float*)d_in[5];
    const float* b2  = (const float*)d_in[6];
    const float* g2  = (const float*)d_in[7];
    const float* be2 = (const float*)d_in[8];
    const float* w3  = (const float*)d_in[9];
    const float* b3  = (const float*)d_in[10];
    const float* g3  = (const float*)d_in[11];
    const float* be3 = (const float*)d_in[12];
    const float* w4  = (const float*)d_in[13];
    const float* b4  = (const float*)d_in[14];
    const float* g4  = (const float*)d_in[15];
    const float* be4 = (const float*)d_in[16];
    const float* w5  = (const float*)d_in[17];
    const float* b5  = (const float*)d_in[18];
    const float* lw  = (const float*)d_in[19];
    const float* lb  = (const float*)d_in[20];
    const float* bw  = (const float*)d_in[21];
    const float* aw  = (const float*)d_in[22];
    const float* ab  = (const float*)d_in[23];

    float *res, *x1, *x2, *x3, *x4, *codes, *stats, *wts, *verts;
    uint4* lutC;
    cudaGetSymbolAddress((void**)&res,   g_resized);
    cudaGetSymbolAddress((void**)&x1,    g_x1);
    cudaGetSymbolAddress((void**)&x2,    g_x2);
    cudaGetSymbolAddress((void**)&x3,    g_x3);
    cudaGetSymbolAddress((void**)&x4,    g_x4);
    cudaGetSymbolAddress((void**)&codes, g_codes);
    cudaGetSymbolAddress((void**)&stats, g_stats);
    cudaGetSymbolAddress((void**)&wts,   g_wts);
    cudaGetSymbolAddress((void**)&verts, g_verts);
    cudaGetSymbolAddress((void**)&lutC,  g_lutC);

    float* ss1 = stats;          // 4*16*2  = 128
    float* ss2 = stats + 128;    // 4*32*2  = 256
    float* ss3 = stats + 384;    // 4*64*2  = 512
    float* ss4 = stats + 896;    // 4*128*2 = 1024

    float* out = (float*)d_out;
    const int OFF_W = B*3*NPIX;
    const int OFF_V = OFF_W + B*3;

    resize_k<<<(B*3*256*256 + 255)/256, 256>>>(lq, res, stats);

    conv_k<3, 16, 8, 256, 128, false><<<dim3(64, 2, B), 256>>>(
        res, w1, b1, nullptr, nullptr, nullptr, ss1, x1);

    conv_k<16, 32, 4, 128, 64, true><<<dim3(16, 8, B), 256>>>(
        x1, w2, b2, ss1, g1, be1, ss2, x2);

    conv_k<32, 64, 2, 64, 32, true><<<dim3(4, 32, B), 256>>>(
        x2, w3, b3, ss2, g2, be2, ss3, x3);

    conv_k<64, 128, 2, 32, 16, true><<<dim3(1, 64, B), 256>>>(
        x3, w4, b4, ss3, g3, be3, ss4, x4);

    conv5_pool_k<<<dim3(32, B), 256>>>(x4, w5, b5, ss4, g4, be4, codes);

    mlp_k<<<B, 256>>>(codes, lw, lb, aw, ab, wts, verts, out + OFF_W, out + OFF_V);

    lutC_k<<<(B*D3 + 255)/256, 256>>>(bw, wts, lutC);

    transform_k<<<B*1024, 256>>>(lq, lutC, verts, out);
}

// round 11
// speedup vs baseline: 1.0443x; 1.0443x over previous
#include <cuda_runtime.h>
#include <cuda_bf16.h>
#include <cuda_fp16.h>
#include <math.h>

#define DV 33
#define D2 (DV*DV)        // 1089
#define D3 (DV*DV*DV)     // 35937
#define B 4
#define NPIX (1024*1024)

// ---------------- scratch ----------------------------------------------------
// feature maps stored DE-INTERLEAVED: per (b,c) plane of HW*HW floats is split
// into even columns [0, HW*HW/2) then odd columns [HW*HW/2, HW*HW)
__device__ float g_resized[B*3*256*256];
__device__ float g_x1[B*16*128*128];
__device__ float g_x2[B*32*64*64];
__device__ float g_x3[B*64*32*32];
__device__ float g_x4[B*128*16*16];
__device__ float g_codes[B*512];
// raw stats per (b,c): [sum,sumsq]: ss1@0(128) ss2@128(256) ss3@384(512) ss4@896(1024)
__device__ float g_stats[1920];
__device__ float g_wts[B*3];
__device__ float g_verts[B*3*DV];
// cube-packed LUT: per (b,i,j,k) one 32B record =
//   [f32 min][f32 scale][24 x u8 q], q idx = 3*(di*4+dj*2+dk)+ch
__device__ uint4 g_lutC[B*D3*2];

// ---------------- resize (+ stats zeroing): 1024->256, de-interleaved out ----
__global__ void resize_k(const float* __restrict__ lq, float* __restrict__ out,
                         float* __restrict__ stats)
{
    int idx = blockIdx.x * blockDim.x + threadIdx.x;
    if (idx < 1920) stats[idx] = 0.f;
    if (idx >= B*3*256*256) return;
    int ox = idx & 255;
    int oy = (idx >> 8) & 255;
    int bc = idx >> 16;
    const float* ip = lq + (size_t)bc * 1024 * 1024 + (size_t)(4*oy+1)*1024 + (4*ox+1);
    float v = 0.25f * (ip[0] + ip[1] + ip[1024] + ip[1025]);
    out[(size_t)bc*65536 + (ox & 1)*32768 + oy*128 + (ox >> 1)] = v;
}

// ---------------- direct conv: k3 s2 p1 + LeakyReLU; de-interleaved I/O ------
template<int IC, int OC, int OCB, int INHW, int OUTHW, bool HAS_IN>
__global__ void __launch_bounds__(256) conv_k(
                       const float* __restrict__ in, const float* __restrict__ w,
                       const float* __restrict__ bias,
                       const float* __restrict__ stat_in,
                       const float* __restrict__ gamma, const float* __restrict__ beta,
                       float* __restrict__ stat_out,
                       float* __restrict__ out)
{
    const int HW2 = INHW/2;
    const int HALF = INHW*INHW/2;
    const int OHALF = OUTHW*OUTHW/2;
    const int b = blockIdx.z;
    const int ocg = blockIdx.y;
    const int tid = threadIdx.x;
    __shared__ float sw[IC*9*OCB];
    __shared__ float ssc[IC];
    __shared__ float ssh[IC];
    for (int i = tid; i < IC*9*OCB; i += 256) {
        int o = i % OCB, t = i / OCB;
        int k = t % 9, ic = t / 9;
        sw[i] = w[((ocg*OCB + o)*IC + ic)*9 + k];
    }
    if (HAS_IN) {
        for (int i = tid; i < IC; i += 256) {
            const float invn = 1.f / (float)(INHW*INHW);
            float s1 = stat_in[(b*IC+i)*2], s2 = stat_in[(b*IC+i)*2+1];
            float mean = s1 * invn;
            float var  = s2 * invn - mean*mean;
            float sc = gamma[i] * rsqrtf(var + 1e-5f);
            ssc[i] = sc;
            ssh[i] = beta[i] - mean * sc;
        }
    }
    __syncthreads();

    int p = blockIdx.x*256 + tid;         // OUTHW*OUTHW multiple of 256
    int oy = p / OUTHW, ox = p % OUTHW;
    float acc[OCB];
    #pragma unroll
    for (int o = 0; o < OCB; o++) acc[o] = bias[ocg*OCB+o];

    const bool okT = (oy > 0);
    const bool okL = (ox > 0);
    const float* inb = in + (size_t)b*IC*INHW*INHW + (2*oy-1)*HW2 + ox;

    for (int ic = 0; ic < IC; ic++) {
        const float* ipE = inb + (size_t)ic*INHW*INHW;
        const float* ipO = ipE + HALF;
        float v[9];
        #pragma unroll
        for (int ky = 0; ky < 3; ky++) {
            bool okR = (okT || ky > 0);
            int off = ky*HW2;
            v[ky*3+0] = (okR && okL) ? ipO[off-1] : 0.f;
            v[ky*3+1] = okR          ? ipE[off]   : 0.f;
            v[ky*3+2] = okR          ? ipO[off]   : 0.f;
        }
        if (HAS_IN) {
            float s = ssc[ic], sh = ssh[ic];
            #pragma unroll
            for (int ky = 0; ky < 3; ky++) {
                bool okR = (okT || ky > 0);
                v[ky*3+0] = (okR && okL) ? fmaf(v[ky*3+0], s, sh) : 0.f;
                v[ky*3+1] = okR          ? fmaf(v[ky*3+1], s, sh) : 0.f;
                v[ky*3+2] = okR          ? fmaf(v[ky*3+2], s, sh) : 0.f;
            }
        }
        #pragma unroll
        for (int k = 0; k < 9; k++) {
            float t = v[k];
            #pragma unroll
            for (int o = 0; o < OCB; o++)
                acc[o] = fmaf(t, sw[(ic*9+k)*OCB+o], acc[o]);
        }
    }

    const size_t oaddr = (ox & 1)*OHALF + oy*(OUTHW/2) + (ox >> 1);
    float ys[OCB];
    #pragma unroll
    for (int o = 0; o < OCB; o++) {
        float y = acc[o];
        y = y >= 0.f ? y : 0.2f*y;
        ys[o] = y;
        out[((size_t)b*OC + ocg*OCB + o)*OUTHW*OUTHW + oaddr] = y;
    }

    float s1[OCB], s2[OCB];
    #pragma unroll
    for (int o = 0; o < OCB; o++) { s1[o] = ys[o]; s2[o] = ys[o]*ys[o]; }
    #pragma unroll
    for (int o = 0; o < OCB; o++) {
        #pragma unroll
        for (int off = 16; off; off >>= 1) {
            s1[o] += __shfl_xor_sync(0xffffffffu, s1[o], off);
            s2[o] += __shfl_xor_sync(0xffffffffu, s2[o], off);
        }
    }
    __shared__ float2 red[OCB][8];
    int warp = tid >> 5, lane = tid & 31;
    if (lane == 0) {
        #pragma unroll
        for (int o = 0; o < OCB; o++) red[o][warp] = make_float2(s1[o], s2[o]);
    }
    __syncthreads();
    if (tid < OCB) {
        float a = 0.f, c = 0.f;
        #pragma unroll
        for (int wdx = 0; wdx < 8; wdx++) { a += red[tid][wdx].x; c += red[tid][wdx].y; }
        int bc = b*OC + ocg*OCB + tid;
        atomicAdd(stat_out + bc*2, a);
        atomicAdd(stat_out + bc*2+1, c);
    }
}

// ---------------- conv5 + LeakyReLU + avgpool(2) -> codes (de-interleaved in)
// grid (32, B): 32 oc-groups of 4; 256 thr = 64 px x 4 osub (1 oc each)
__global__ void __launch_bounds__(256) conv5_pool_k(
                             const float* __restrict__ in, const float* __restrict__ w,
                             const float* __restrict__ bias,
                             const float* __restrict__ stat_in,
                             const float* __restrict__ gamma, const float* __restrict__ beta,
                             float* __restrict__ codes)
{
    const int IC = 128, OCPB = 4;
    const int b = blockIdx.y, ocg = blockIdx.x;
    const int tid = threadIdx.x;
    const int px = tid & 63, osub = tid >> 6;
    const int oy = px >> 3, ox = px & 7;

    __shared__ float sw[IC*9*OCPB];
    __shared__ float ssc[IC], ssh[IC];
    __shared__ float sred[OCPB][64];

    for (int i = tid; i < IC; i += 256) {
        const float invn = 1.f / 256.f;
        float s1 = stat_in[(b*IC+i)*2], s2 = stat_in[(b*IC+i)*2+1];
        float mean = s1 * invn;
        float var  = s2 * invn - mean*mean;
        float sc = gamma[i] * rsqrtf(var + 1e-5f);
        ssc[i] = sc;
        ssh[i] = beta[i] - mean * sc;
    }
    for (int i = tid; i < IC*9*OCPB; i += 256) {
        int o = i % OCPB, t = i / OCPB;
        int k = t % 9, ic = t / 9;
        sw[i] = w[((ocg*OCPB + o)*IC + ic)*9 + k];
    }
    __syncthreads();

    float acc = bias[ocg*OCPB + osub];

    const bool okT = (oy > 0), okL = (ox > 0);
    const float* inb = in + (size_t)b*IC*256 + (2*oy-1)*8 + ox;

    for (int ic = 0; ic < IC; ic++) {
        const float* ipE = inb + ic*256;
        const float* ipO = ipE + 128;
        float s = ssc[ic], sh = ssh[ic];
        float v[9];
        #pragma unroll
        for (int ky = 0; ky < 3; ky++) {
            bool okR = (okT || ky > 0);
            int off = ky*8;
            float l = (okR && okL) ? ipO[off-1] : 0.f;
            float m = okR          ? ipE[off]   : 0.f;
            float r = okR          ? ipO[off]   : 0.f;
            v[ky*3+0] = (okR && okL) ? fmaf(l, s, sh) : 0.f;
            v[ky*3+1] = okR          ? fmaf(m, s, sh) : 0.f;
            v[ky*3+2] = okR          ? fmaf(r, s, sh) : 0.f;
        }
        #pragma unroll
        for (int k = 0; k < 9; k++)
            acc = fmaf(v[k], sw[(ic*9+k)*OCPB + osub], acc);
    }

    sred[osub][px] = acc >= 0.f ? acc : 0.2f*acc;
    __syncthreads();
    if (tid < 16) {
        int o = tid >> 2, q = tid & 3, py = q >> 1, qx = q & 1;
        float s = 0.f;
        #pragma unroll
        for (int yy = 0; yy < 4; yy++)
            #pragma unroll
            for (int xx = 0; xx < 4; xx++)
                s += sred[o][(py*4+yy)*8 + (qx*4+xx)];
        codes[b*512 + (ocg*OCPB + o)*4 + q] = s * (1.f/16.f);
    }
}

// ---------------- LUT weights + AdaInt vertices (warp-per-row GEMV) ----------
__global__ void mlp_k(const float* __restrict__ codes,
                      const float* __restrict__ lw, const float* __restrict__ lb,
                      const float* __restrict__ aw, const float* __restrict__ ab,
                      float* __restrict__ wts, float* __restrict__ verts,
                      float* __restrict__ out_w, float* __restrict__ out_v)
{
    int b = blockIdx.x;
    __shared__ float sc[512];
    __shared__ float pre[96];
    int t = threadIdx.x;
    int warp = t >> 5, lane = t & 31;
    for (int i = t; i < 512; i += 256) sc[i] = codes[b*512 + i];
    __syncthreads();

    // 99 rows: 0..95 -> aw (pre), 96..98 -> lw (wts)
    for (int r = warp; r < 99; r += 8) {
        const float* row = (r < 96) ? (aw + (size_t)r*512) : (lw + (size_t)(r-96)*512);
        float acc = 0.f;
        #pragma unroll
        for (int k = 0; k < 16; k++)
            acc = fmaf(sc[lane + k*32], row[lane + k*32], acc);
        #pragma unroll
        for (int off = 16; off; off >>= 1)
            acc += __shfl_xor_sync(0xffffffffu, acc, off);
        if (lane == 0) {
            if (r < 96) pre[r] = acc + ab[r];
            else {
                float v = acc + lb[r-96];
                wts[b*3 + (r-96)] = v;
                out_w[b*3 + (r-96)] = v;
            }
        }
    }
    __syncthreads();

    if (warp < 3) {
        float x = pre[warp*32 + lane];
        float m = x;
        #pragma unroll
        for (int off = 16; off; off >>= 1) m = fmaxf(m, __shfl_xor_sync(0xffffffffu, m, off));
        float e = expf(x - m);
        float ssum = e;
        #pragma unroll
        for (int off = 16; off; off >>= 1) ssum += __shfl_xor_sync(0xffffffffu, ssum, off);
        float p = e / ssum;
        float cs = p;
        #pragma unroll
        for (int off = 1; off < 32; off <<= 1) {
            float v = __shfl_up_sync(0xffffffffu, cs, off);
            if (lane >= off) cs += v;
        }
        float* vp = verts + (b*3 + warp)*DV;
        float* vo = out_v + (b*3 + warp)*DV;
        if (lane == 0) { vp[0] = 0.f; vo[0] = 0.f; }
        vp[lane+1] = cs;
        vo[lane+1] = cs;
    }
}

// ---------------- lut synthesis into cube-packed u8 records ------------------
__global__ void lutC_k(const float* __restrict__ bw, const float* __restrict__ wts,
                       uint4* __restrict__ lutC)
{
    int i = blockIdx.x*blockDim.x + threadIdx.x;
    if (i >= B*D3) return;
    int b = i / D3, s = i - b*D3;
    int k = s % DV;
    int j = (s / DV) % DV;
    int ii = s / D2;
    int di = (ii < DV-1) ? D2 : 0;
    int dj = (j  < DV-1) ? DV : 0;
    int dk = (k  < DV-1) ? 1  : 0;
    float w0 = wts[b*3], w1 = wts[b*3+1], w2 = wts[b*3+2];

    float vals[24];
    #pragma unroll
    for (int a = 0; a < 2; a++)
        #pragma unroll
        for (int c = 0; c < 2; c++)
            #pragma unroll
            for (int d = 0; d < 2; d++) {
                int idx = s + a*di + c*dj + d*dk;
                int corner = a*4 + c*2 + d;
                #pragma unroll
                for (int ch = 0; ch < 3; ch++) {
                    const float* p = bw + ((size_t)ch*D3 + idx)*3;
                    vals[corner*3 + ch] = fmaf(w0, p[0], fmaf(w1, p[1], w2*p[2]));
                }
            }

    float mn = vals[0], mx = vals[0];
    #pragma unroll
    for (int t = 1; t < 24; t++) { mn = fminf(mn, vals[t]); mx = fmaxf(mx, vals[t]); }
    float scale = (mx - mn) * (1.f/255.f);
    float inv = (scale > 0.f) ? 1.f/scale : 0.f;

    unsigned int u[6];
    #pragma unroll
    for (int wd = 0; wd < 6; wd++) {
        unsigned int r = 0;
        #pragma unroll
        for (int bb = 0; bb < 4; bb++) {
            int t = wd*4 + bb;
            int q = __float2int_rn((vals[t] - mn) * inv);
            q = min(max(q, 0), 255);
            r |= ((unsigned int)q) << (8*bb);
        }
        u[wd] = r;
    }
    uint4 lo, hi;
    lo.x = __float_as_uint(mn);
    lo.y = __float_as_uint(scale);
    lo.z = u[0]; lo.w = u[1];
    hi.x = u[2]; hi.y = u[3]; hi.z = u[4]; hi.w = u[5];
    lutC[(size_t)i*2]   = lo;
    lutC[(size_t)i*2+1] = hi;
}

// ---------------- AiLUT transform: record-table searchsorted + cube trilerp --
__global__ void __launch_bounds__(256) transform_k(
                            const float* __restrict__ lq, const uint4* __restrict__ lutC,
                            const float* __restrict__ verts, float* __restrict__ out)
{
    int b = blockIdx.x >> 10;
    int blk = blockIdx.x & 1023;
    int tid = threadIdx.x;
    __shared__ float sv[3][DV];
    __shared__ float4 s_int[3][33];    // per-interval: (vlo, inv, basef, vhi)
    __shared__ float4 s_edge[3][128];  // per 1/128-bin: record of left-edge interval
    if (tid < 99) sv[tid/33][tid%33] = verts[b*99 + tid];
    __syncthreads();
    // build interval records (intervals 1..32)
    if (tid < 96) {
        int ch = tid / 32, idx = (tid & 31) + 1;
        float vlo = sv[ch][idx-1], vhi = sv[ch][idx];
        float4 r;
        r.x = vlo;
        r.y = 1.f / (vhi - vlo + 1e-8f);
        r.z = (float)(idx - 1);
        r.w = (idx == 32) ? __int_as_float(0x7f800000) : vhi;  // +inf guard on last
        s_int[ch][idx] = r;
    }
    __syncthreads();
    // build edge table
    for (int t = tid; t < 384; t += 256) {
        int ch = t >> 7, e = t & 127;
        float edge = (float)e * (1.f/128.f);
        int idx = 0;
        #pragma unroll 8
        for (int m = 1; m <= 32; m++)
            if (sv[ch][m] <= edge) idx = m;
        s_edge[ch][e] = s_int[ch][min(idx, 31) + 1];
    }
    __syncthreads();

    int n = (blk*256 + tid) * 4;
    const float* lqb = lq + (size_t)b*3*NPIX;
    float4 R  = *(const float4*)(lqb + n);
    float4 G  = *(const float4*)(lqb + NPIX + n);
    float4 Bl = *(const float4*)(lqb + 2*NPIX + n);

    float xr[4] = {R.x, R.y, R.z, R.w};
    float xg[4] = {G.x, G.y, G.z, G.w};
    float xb[4] = {Bl.x, Bl.y, Bl.z, Bl.w};
    float orr[4], org[4], orb[4];

    const uint4* base = lutC + (size_t)b*D3*2;

    #pragma unroll
    for (int px = 0; px < 4; px++) {
        int i0, j0, k0;
        float fr, fg, fb;
        float xs[3] = {xr[px], xg[px], xb[px]};
        #pragma unroll
        for (int ch = 0; ch < 3; ch++) {
            float x = xs[ch];
            int e = min((int)(x * 128.f), 127);
            float4 rec = s_edge[ch][e];
            while (x > rec.w)
                rec = s_int[ch][(int)rec.z + 2];
            float f = fminf((x - rec.x) * rec.y, 1.f);
            int cb = (int)rec.z;
            if (ch == 0) { i0 = cb; fr = f; }
            else if (ch == 1) { j0 = cb; fg = f; }
            else { k0 = cb; fb = f; }
        }

        size_t e0 = (size_t)(i0*D2 + j0*DV + k0)*2;
        uint4 lo4 = base[e0];
        uint4 hi4 = base[e0+1];
        float mn = __uint_as_float(lo4.x);
        float sc = __uint_as_float(lo4.y);
        unsigned int u[6] = {lo4.z, lo4.w, hi4.x, hi4.y, hi4.z, hi4.w};

        #pragma unroll
        for (int ch = 0; ch < 3; ch++) {
            float q[8];
            #pragma unroll
            for (int corner = 0; corner < 8; corner++) {
                int t = corner*3 + ch;
                q[corner] = (float)((u[t >> 2] >> ((t & 3)*8)) & 0xffu);
            }
            // corner = di*4 + dj*2 + dk
            float l00 = fmaf(fb, q[1] - q[0], q[0]);
            float l01 = fmaf(fb, q[3] - q[2], q[2]);
            float l10 = fmaf(fb, q[5] - q[4], q[4]);
            float l11 = fmaf(fb, q[7] - q[6], q[6]);
            float h0  = fmaf(fg, l01 - l00, l00);
            float h1  = fmaf(fg, l11 - l10, l10);
            float vq  = fmaf(fr, h1 - h0, h0);
            float v   = fmaf(sc, vq, mn);
            v = fminf(fmaxf(v, 0.f), 1.f);
            if (ch == 0) orr[px] = v; else if (ch == 1) org[px] = v; else orb[px] = v;
        }
    }

    float* ob = out + (size_t)b*3*NPIX + n;
    *(float4*)(ob)          = make_float4(orr[0], orr[1], orr[2], orr[3]);
    *(float4*)(ob + NPIX)   = make_float4(org[0], org[1], org[2], org[3]);
    *(float4*)(ob + 2*NPIX) = make_float4(orb[0], orb[1], orb[2], orb[3]);
}

// ---------------- host launcher ----------------------------------------------
extern "C" void kernel_launch(void* const* d_in, const int* in_sizes, int n_in,
                              void* d_out, int out_size)
{
    const float* lq  = (const float*)d_in[0];
    const float* w1  = (const float*)d_in[1];
    const float* b1  = (const float*)d_in[2];
    const float* g1  = (const float*)d_in[3];
    const float* be1 = (const float*)d_in[4];
    const float* w2  = (const float*)d_in[5];
    const float* b2  = (const float*)d_in[6];
    const float* g2  = (const float*)d_in[7];
    const float* be2 = (const float*)d_in[8];
    const float* w3  = (const float*)d_in[9];
    const float* b3  = (const float*)d_in[10];
    const float* g3  = (const float*)d_in[11];
    const float* be3 = (const float*)d_in[12];
    const float* w4  = (const float*)d_in[13];
    const float* b4  = (const float*)d_in[14];
    const float* g4  = (const float*)d_in[15];
    const float* be4 = (const float*)d_in[16];
    const float* w5  = (const float*)d_in[17];
    const float* b5  = (const float*)d_in[18];
    const float* lw  = (const float*)d_in[19];
    const float* lb  = (const float*)d_in[20];
    const float* bw  = (const float*)d_in[21];
    const float* aw  = (const float*)d_in[22];
    const float* ab  = (const float*)d_in[23];

    float *res, *x1, *x2, *x3, *x4, *codes, *stats, *wts, *verts;
    uint4* lutC;
    cudaGetSymbolAddress((void**)&res,   g_resized);
    cudaGetSymbolAddress((void**)&x1,    g_x1);
    cudaGetSymbolAddress((void**)&x2,    g_x2);
    cudaGetSymbolAddress((void**)&x3,    g_x3);
    cudaGetSymbolAddress((void**)&x4,    g_x4);
    cudaGetSymbolAddress((void**)&codes, g_codes);
    cudaGetSymbolAddress((void**)&stats, g_stats);
    cudaGetSymbolAddress((void**)&wts,   g_wts);
    cudaGetSymbolAddress((void**)&verts, g_verts);
    cudaGetSymbolAddress((void**)&lutC,  g_lutC);

    float* ss1 = stats;          // 4*16*2  = 128
    float* ss2 = stats + 128;    // 4*32*2  = 256
    float* ss3 = stats + 384;    // 4*64*2  = 512
    float* ss4 = stats + 896;    // 4*128*2 = 1024

    float* out = (float*)d_out;
    const int OFF_W = B*3*NPIX;
    const int OFF_V = OFF_W + B*3;

    resize_k<<<(B*3*256*256 + 255)/256, 256>>>(lq, res, stats);

    conv_k<3, 16, 8, 256, 128, false><<<dim3(64, 2, B), 256>>>(
        res, w1, b1, nullptr, nullptr, nullptr, ss1, x1);

    conv_k<16, 32, 4, 128, 64, true><<<dim3(16, 8, B), 256>>>(
        x1, w2, b2, ss1, g1, be1, ss2, x2);

    conv_k<32, 64, 4, 64, 32, true><<<dim3(4, 16, B), 256>>>(
        x2, w3, b3, ss2, g2, be2, ss3, x3);

    conv_k<64, 128, 4, 32, 16, true><<<dim3(1, 32, B), 256>>>(
        x3, w4, b4, ss3, g3, be3, ss4, x4);

    conv5_pool_k<<<dim3(32, B), 256>>>(x4, w5, b5, ss4, g4, be4, codes);

    mlp_k<<<B, 256>>>(codes, lw, lb, aw, ab, wts, verts, out + OFF_W, out + OFF_V);

    lutC_k<<<(B*D3 + 255)/256, 256>>>(bw, wts, lutC);

    transform_k<<<B*1024, 256>>>(lq, lutC, verts, out);
}

// round 12
// speedup vs baseline: 1.1785x; 1.1286x over previous
#include <cuda_runtime.h>
#include <cuda_bf16.h>
#include <cuda_fp16.h>
#include <math.h>

#define DV 33
#define D2 (DV*DV)        // 1089
#define D3 (DV*DV*DV)     // 35937
#define B 4
#define NPIX (1024*1024)

// ---------------- scratch ----------------------------------------------------
// feature maps stored DE-INTERLEAVED: per (b,c) plane of HW*HW floats is split
// into even columns [0, HW*HW/2) then odd columns [HW*HW/2, HW*HW)
__device__ float g_resized[B*3*256*256];
__device__ float g_x1[B*16*128*128];
__device__ float g_x2[B*32*64*64];
__device__ float g_x3[B*64*32*32];
__device__ float g_x4[B*128*16*16];
__device__ float g_partA[B*64*32*32];   // split-IC partial buffers (max: conv3)
__device__ float g_partB[B*64*32*32];
__device__ float g_codes[B*512];
// raw stats per (b,c): [sum,sumsq]: ss1@0(128) ss2@128(256) ss3@384(512) ss4@896(1024)
__device__ float g_stats[1920];
__device__ float g_wts[B*3];
__device__ float g_verts[B*3*DV];
// cube-packed LUT: per (b,i,j,k) one 32B record =
//   [f32 min][f32 scale][24 x u8 q], q idx = 3*(di*4+dj*2+dk)+ch
__device__ uint4 g_lutC[B*D3*2];

// ---------------- resize (+ stats zeroing): 1024->256, de-interleaved out ----
__global__ void resize_k(const float* __restrict__ lq, float* __restrict__ out,
                         float* __restrict__ stats)
{
    int idx = blockIdx.x * blockDim.x + threadIdx.x;
    if (idx < 1920) stats[idx] = 0.f;
    if (idx >= B*3*256*256) return;
    int ox = idx & 255;
    int oy = (idx >> 8) & 255;
    int bc = idx >> 16;
    const float* ip = lq + (size_t)bc * 1024 * 1024 + (size_t)(4*oy+1)*1024 + (4*ox+1);
    float v = 0.25f * (ip[0] + ip[1] + ip[1024] + ip[1025]);
    out[(size_t)bc*65536 + (ox & 1)*32768 + oy*128 + (ox >> 1)] = v;
}

// ---------------- direct conv: k3 s2 p1 + LeakyReLU; de-interleaved I/O ------
// (used for conv1 and conv2, which have healthy grids)
template<int IC, int OC, int OCB, int INHW, int OUTHW, bool HAS_IN>
__global__ void __launch_bounds__(256) conv_k(
                       const float* __restrict__ in, const float* __restrict__ w,
                       const float* __restrict__ bias,
                       const float* __restrict__ stat_in,
                       const float* __restrict__ gamma, const float* __restrict__ beta,
                       float* __restrict__ stat_out,
                       float* __restrict__ out)
{
    const int HW2 = INHW/2;
    const int HALF = INHW*INHW/2;
    const int OHALF = OUTHW*OUTHW/2;
    const int b = blockIdx.z;
    const int ocg = blockIdx.y;
    const int tid = threadIdx.x;
    __shared__ float sw[IC*9*OCB];
    __shared__ float ssc[IC];
    __shared__ float ssh[IC];
    for (int i = tid; i < IC*9*OCB; i += 256) {
        int o = i % OCB, t = i / OCB;
        int k = t % 9, ic = t / 9;
        sw[i] = w[((ocg*OCB + o)*IC + ic)*9 + k];
    }
    if (HAS_IN) {
        for (int i = tid; i < IC; i += 256) {
            const float invn = 1.f / (float)(INHW*INHW);
            float s1 = stat_in[(b*IC+i)*2], s2 = stat_in[(b*IC+i)*2+1];
            float mean = s1 * invn;
            float var  = s2 * invn - mean*mean;
            float sc = gamma[i] * rsqrtf(var + 1e-5f);
            ssc[i] = sc;
            ssh[i] = beta[i] - mean * sc;
        }
    }
    __syncthreads();

    int p = blockIdx.x*256 + tid;
    int oy = p / OUTHW, ox = p % OUTHW;
    float acc[OCB];
    #pragma unroll
    for (int o = 0; o < OCB; o++) acc[o] = bias[ocg*OCB+o];

    const bool okT = (oy > 0);
    const bool okL = (ox > 0);
    const float* inb = in + (size_t)b*IC*INHW*INHW + (2*oy-1)*HW2 + ox;

    for (int ic = 0; ic < IC; ic++) {
        const float* ipE = inb + (size_t)ic*INHW*INHW;
        const float* ipO = ipE + HALF;
        float v[9];
        #pragma unroll
        for (int ky = 0; ky < 3; ky++) {
            bool okR = (okT || ky > 0);
            int off = ky*HW2;
            v[ky*3+0] = (okR && okL) ? ipO[off-1] : 0.f;
            v[ky*3+1] = okR          ? ipE[off]   : 0.f;
            v[ky*3+2] = okR          ? ipO[off]   : 0.f;
        }
        if (HAS_IN) {
            float s = ssc[ic], sh = ssh[ic];
            #pragma unroll
            for (int ky = 0; ky < 3; ky++) {
                bool okR = (okT || ky > 0);
                v[ky*3+0] = (okR && okL) ? fmaf(v[ky*3+0], s, sh) : 0.f;
                v[ky*3+1] = okR          ? fmaf(v[ky*3+1], s, sh) : 0.f;
                v[ky*3+2] = okR          ? fmaf(v[ky*3+2], s, sh) : 0.f;
            }
        }
        #pragma unroll
        for (int k = 0; k < 9; k++) {
            float t = v[k];
            #pragma unroll
            for (int o = 0; o < OCB; o++)
                acc[o] = fmaf(t, sw[(ic*9+k)*OCB+o], acc[o]);
        }
    }

    const size_t oaddr = (ox & 1)*OHALF + oy*(OUTHW/2) + (ox >> 1);
    float ys[OCB];
    #pragma unroll
    for (int o = 0; o < OCB; o++) {
        float y = acc[o];
        y = y >= 0.f ? y : 0.2f*y;
        ys[o] = y;
        out[((size_t)b*OC + ocg*OCB + o)*OUTHW*OUTHW + oaddr] = y;
    }

    float s1[OCB], s2[OCB];
    #pragma unroll
    for (int o = 0; o < OCB; o++) { s1[o] = ys[o]; s2[o] = ys[o]*ys[o]; }
    #pragma unroll
    for (int o = 0; o < OCB; o++) {
        #pragma unroll
        for (int off = 16; off; off >>= 1) {
            s1[o] += __shfl_xor_sync(0xffffffffu, s1[o], off);
            s2[o] += __shfl_xor_sync(0xffffffffu, s2[o], off);
        }
    }
    __shared__ float2 red[OCB][8];
    int warp = tid >> 5, lane = tid & 31;
    if (lane == 0) {
        #pragma unroll
        for (int o = 0; o < OCB; o++) red[o][warp] = make_float2(s1[o], s2[o]);
    }
    __syncthreads();
    if (tid < OCB) {
        float a = 0.f, c = 0.f;
        #pragma unroll
        for (int wdx = 0; wdx < 8; wdx++) { a += red[tid][wdx].x; c += red[tid][wdx].y; }
        int bc = b*OC + ocg*OCB + tid;
        atomicAdd(stat_out + bc*2, a);
        atomicAdd(stat_out + bc*2+1, c);
    }
}

// ---------------- split-IC partial conv (no bias/leaky/stats) ----------------
// grid.x = SPB*2 (spatial blocks x 2 IC halves); writes raw partial sums.
template<int IC, int OC, int OCB, int INHW, int OUTHW>
__global__ void __launch_bounds__(256) conv_part_k(
                       const float* __restrict__ in, const float* __restrict__ w,
                       const float* __restrict__ stat_in,
                       const float* __restrict__ gamma, const float* __restrict__ beta,
                       float* __restrict__ partA, float* __restrict__ partB)
{
    const int SPB = OUTHW*OUTHW/256;
    const int ICH = IC/2;
    const int HW2 = INHW/2;
    const int HALF = INHW*INHW/2;
    const int OHALF = OUTHW*OUTHW/2;
    const int b = blockIdx.z;
    const int ocg = blockIdx.y;
    const int sp = blockIdx.x % SPB;
    const int half = blockIdx.x / SPB;
    const int ic0 = half * ICH;
    const int tid = threadIdx.x;
    float* part = half ? partB : partA;

    __shared__ float sw[ICH*9*OCB];
    __shared__ float ssc[ICH];
    __shared__ float ssh[ICH];
    for (int i = tid; i < ICH*9*OCB; i += 256) {
        int o = i % OCB, t = i / OCB;
        int k = t % 9, icl = t / 9;
        sw[i] = w[((ocg*OCB + o)*IC + ic0 + icl)*9 + k];
    }
    for (int i = tid; i < ICH; i += 256) {
        const float invn = 1.f / (float)(INHW*INHW);
        int c = ic0 + i;
        float s1 = stat_in[(b*IC+c)*2], s2 = stat_in[(b*IC+c)*2+1];
        float mean = s1 * invn;
        float var  = s2 * invn - mean*mean;
        float sc = gamma[c] * rsqrtf(var + 1e-5f);
        ssc[i] = sc;
        ssh[i] = beta[c] - mean * sc;
    }
    __syncthreads();

    int p = sp*256 + tid;
    int oy = p / OUTHW, ox = p % OUTHW;
    float acc[OCB];
    #pragma unroll
    for (int o = 0; o < OCB; o++) acc[o] = 0.f;

    const bool okT = (oy > 0);
    const bool okL = (ox > 0);
    const float* inb = in + ((size_t)b*IC + ic0)*INHW*INHW + (2*oy-1)*HW2 + ox;

    for (int icl = 0; icl < ICH; icl++) {
        const float* ipE = inb + (size_t)icl*INHW*INHW;
        const float* ipO = ipE + HALF;
        float s = ssc[icl], sh = ssh[icl];
        float v[9];
        #pragma unroll
        for (int ky = 0; ky < 3; ky++) {
            bool okR = (okT || ky > 0);
            int off = ky*HW2;
            float l = (okR && okL) ? ipO[off-1] : 0.f;
            float m = okR          ? ipE[off]   : 0.f;
            float r = okR          ? ipO[off]   : 0.f;
            v[ky*3+0] = (okR && okL) ? fmaf(l, s, sh) : 0.f;
            v[ky*3+1] = okR          ? fmaf(m, s, sh) : 0.f;
            v[ky*3+2] = okR          ? fmaf(r, s, sh) : 0.f;
        }
        #pragma unroll
        for (int k = 0; k < 9; k++) {
            float t = v[k];
            #pragma unroll
            for (int o = 0; o < OCB; o++)
                acc[o] = fmaf(t, sw[(icl*9+k)*OCB+o], acc[o]);
        }
    }

    const size_t oaddr = (ox & 1)*OHALF + oy*(OUTHW/2) + (ox >> 1);
    #pragma unroll
    for (int o = 0; o < OCB; o++)
        part[((size_t)b*OC + ocg*OCB + o)*OUTHW*OUTHW + oaddr] = acc[o];
}

// ---------------- finalize: combine halves + bias + leaky + stats ------------
// one block per (b,c) plane; writes final x and raw stats (no atomics)
template<int C, int HW>
__global__ void __launch_bounds__(256) stats_fin_k(
        const float* __restrict__ pa, const float* __restrict__ pb,
        const float* __restrict__ bias,
        float* __restrict__ x, float* __restrict__ ss)
{
    const int N = HW*HW;
    int bc = blockIdx.x;
    int c = bc % C;
    float bc_bias = bias[c];
    int tid = threadIdx.x;
    const float* a = pa + (size_t)bc*N;
    const float* bq = pb + (size_t)bc*N;
    float* xo = x + (size_t)bc*N;
    float s1 = 0.f, s2 = 0.f;
    for (int i = tid; i < N; i += 256) {
        float y = a[i] + bq[i] + bc_bias;
        y = y >= 0.f ? y : 0.2f*y;
        xo[i] = y;
        s1 += y;
        s2 += y*y;
    }
    #pragma unroll
    for (int off = 16; off; off >>= 1) {
        s1 += __shfl_xor_sync(0xffffffffu, s1, off);
        s2 += __shfl_xor_sync(0xffffffffu, s2, off);
    }
    __shared__ float2 red[8];
    int warp = tid >> 5, lane = tid & 31;
    if (lane == 0) red[warp] = make_float2(s1, s2);
    __syncthreads();
    if (tid == 0) {
        float a1 = 0.f, a2 = 0.f;
        #pragma unroll
        for (int wdx = 0; wdx < 8; wdx++) { a1 += red[wdx].x; a2 += red[wdx].y; }
        ss[bc*2]   = a1;
        ss[bc*2+1] = a2;
    }
}

// ---------------- conv5 partial (split-IC): raw partial sums -----------------
// grid (64, B): ocg = bx%32, half = bx/32; 256 thr = 64 px x 4 osub (1 oc each)
__global__ void __launch_bounds__(256) conv5_part_k(
                             const float* __restrict__ in, const float* __restrict__ w,
                             const float* __restrict__ stat_in,
                             const float* __restrict__ gamma, const float* __restrict__ beta,
                             float* __restrict__ partA, float* __restrict__ partB)
{
    const int IC = 128, ICH = 64, OCPB = 4;
    const int b = blockIdx.y;
    const int ocg = blockIdx.x & 31;
    const int half = blockIdx.x >> 5;
    const int ic0 = half * ICH;
    const int tid = threadIdx.x;
    const int px = tid & 63, osub = tid >> 6;
    const int oy = px >> 3, ox = px & 7;
    float* part = half ? partB : partA;

    __shared__ float sw[ICH*9*OCPB];
    __shared__ float ssc[ICH], ssh[ICH];

    for (int i = tid; i < ICH; i += 256) {
        const float invn = 1.f / 256.f;
        int c = ic0 + i;
        float s1 = stat_in[(b*IC+c)*2], s2 = stat_in[(b*IC+c)*2+1];
        float mean = s1 * invn;
        float var  = s2 * invn - mean*mean;
        float sc = gamma[c] * rsqrtf(var + 1e-5f);
        ssc[i] = sc;
        ssh[i] = beta[c] - mean * sc;
    }
    for (int i = tid; i < ICH*9*OCPB; i += 256) {
        int o = i % OCPB, t = i / OCPB;
        int k = t % 9, icl = t / 9;
        sw[i] = w[((ocg*OCPB + o)*IC + ic0 + icl)*9 + k];
    }
    __syncthreads();

    float acc = 0.f;
    const bool okT = (oy > 0), okL = (ox > 0);
    const float* inb = in + ((size_t)b*IC + ic0)*256 + (2*oy-1)*8 + ox;

    for (int icl = 0; icl < ICH; icl++) {
        const float* ipE = inb + icl*256;
        const float* ipO = ipE + 128;
        float s = ssc[icl], sh = ssh[icl];
        float v[9];
        #pragma unroll
        for (int ky = 0; ky < 3; ky++) {
            bool okR = (okT || ky > 0);
            int off = ky*8;
            float l = (okR && okL) ? ipO[off-1] : 0.f;
            float m = okR          ? ipE[off]   : 0.f;
            float r = okR          ? ipO[off]   : 0.f;
            v[ky*3+0] = (okR && okL) ? fmaf(l, s, sh) : 0.f;
            v[ky*3+1] = okR          ? fmaf(m, s, sh) : 0.f;
            v[ky*3+2] = okR          ? fmaf(r, s, sh) : 0.f;
        }
        #pragma unroll
        for (int k = 0; k < 9; k++)
            acc = fmaf(v[k], sw[(icl*9+k)*OCPB + osub], acc);
    }

    // part layout: [(b*128 + oc)*64 + px]
    part[((size_t)b*128 + ocg*OCPB + osub)*64 + px] = acc;
}

// ---------------- conv5 pool finalize: leaky + bias + adaptive-avgpool(2) ----
// grid 128 blocks; block handles 4 (b,oc) planes of 64 px
__global__ void __launch_bounds__(256) pool_k(
        const float* __restrict__ pa, const float* __restrict__ pb,
        const float* __restrict__ bias, float* __restrict__ codes)
{
    int tid = threadIdx.x;
    int g = tid >> 6, px = tid & 63;
    int bo = blockIdx.x*4 + g;
    int oc = bo & 127;
    float y = pa[bo*64 + px] + pb[bo*64 + px] + bias[oc];
    y = y >= 0.f ? y : 0.2f*y;
    __shared__ float sred[4][64];
    sred[g][px] = y;
    __syncthreads();
    if (tid < 16) {
        int gg = tid >> 2, q = tid & 3, py = q >> 1, qx = q & 1;
        int bo2 = blockIdx.x*4 + gg;
        int b2 = bo2 >> 7, oc2 = bo2 & 127;
        float s = 0.f;
        #pragma unroll
        for (int yy = 0; yy < 4; yy++)
            #pragma unroll
            for (int xx = 0; xx < 4; xx++)
                s += sred[gg][(py*4+yy)*8 + (qx*4+xx)];
        codes[b2*512 + oc2*4 + q] = s * (1.f/16.f);
    }
}

// ---------------- LUT weights + AdaInt vertices (warp-per-row GEMV) ----------
__global__ void mlp_k(const float* __restrict__ codes,
                      const float* __restrict__ lw, const float* __restrict__ lb,
                      const float* __restrict__ aw, const float* __restrict__ ab,
                      float* __restrict__ wts, float* __restrict__ verts,
                      float* __restrict__ out_w, float* __restrict__ out_v)
{
    int b = blockIdx.x;
    __shared__ float sc[512];
    __shared__ float pre[96];
    int t = threadIdx.x;
    int warp = t >> 5, lane = t & 31;
    for (int i = t; i < 512; i += 256) sc[i] = codes[b*512 + i];
    __syncthreads();

    for (int r = warp; r < 99; r += 8) {
        const float* row = (r < 96) ? (aw + (size_t)r*512) : (lw + (size_t)(r-96)*512);
        float acc = 0.f;
        #pragma unroll
        for (int k = 0; k < 16; k++)
            acc = fmaf(sc[lane + k*32], row[lane + k*32], acc);
        #pragma unroll
        for (int off = 16; off; off >>= 1)
            acc += __shfl_xor_sync(0xffffffffu, acc, off);
        if (lane == 0) {
            if (r < 96) pre[r] = acc + ab[r];
            else {
                float v = acc + lb[r-96];
                wts[b*3 + (r-96)] = v;
                out_w[b*3 + (r-96)] = v;
            }
        }
    }
    __syncthreads();

    if (warp < 3) {
        float x = pre[warp*32 + lane];
        float m = x;
        #pragma unroll
        for (int off = 16; off; off >>= 1) m = fmaxf(m, __shfl_xor_sync(0xffffffffu, m, off));
        float e = expf(x - m);
        float ssum = e;
        #pragma unroll
        for (int off = 16; off; off >>= 1) ssum += __shfl_xor_sync(0xffffffffu, ssum, off);
        float p = e / ssum;
        float cs = p;
        #pragma unroll
        for (int off = 1; off < 32; off <<= 1) {
            float v = __shfl_up_sync(0xffffffffu, cs, off);
            if (lane >= off) cs += v;
        }
        float* vp = verts + (b*3 + warp)*DV;
        float* vo = out_v + (b*3 + warp)*DV;
        if (lane == 0) { vp[0] = 0.f; vo[0] = 0.f; }
        vp[lane+1] = cs;
        vo[lane+1] = cs;
    }
}

// ---------------- lut synthesis into cube-packed u8 records ------------------
__global__ void lutC_k(const float* __restrict__ bw, const float* __restrict__ wts,
                       uint4* __restrict__ lutC)
{
    int i = blockIdx.x*blockDim.x + threadIdx.x;
    if (i >= B*D3) return;
    int b = i / D3, s = i - b*D3;
    int k = s % DV;
    int j = (s / DV) % DV;
    int ii = s / D2;
    int di = (ii < DV-1) ? D2 : 0;
    int dj = (j  < DV-1) ? DV : 0;
    int dk = (k  < DV-1) ? 1  : 0;
    float w0 = wts[b*3], w1 = wts[b*3+1], w2 = wts[b*3+2];

    float vals[24];
    #pragma unroll
    for (int a = 0; a < 2; a++)
        #pragma unroll
        for (int c = 0; c < 2; c++)
            #pragma unroll
            for (int d = 0; d < 2; d++) {
                int idx = s + a*di + c*dj + d*dk;
                int corner = a*4 + c*2 + d;
                #pragma unroll
                for (int ch = 0; ch < 3; ch++) {
                    const float* p = bw + ((size_t)ch*D3 + idx)*3;
                    vals[corner*3 + ch] = fmaf(w0, p[0], fmaf(w1, p[1], w2*p[2]));
                }
            }

    float mn = vals[0], mx = vals[0];
    #pragma unroll
    for (int t = 1; t < 24; t++) { mn = fminf(mn, vals[t]); mx = fmaxf(mx, vals[t]); }
    float scale = (mx - mn) * (1.f/255.f);
    float inv = (scale > 0.f) ? 1.f/scale : 0.f;

    unsigned int u[6];
    #pragma unroll
    for (int wd = 0; wd < 6; wd++) {
        unsigned int r = 0;
        #pragma unroll
        for (int bb = 0; bb < 4; bb++) {
            int t = wd*4 + bb;
            int q = __float2int_rn((vals[t] - mn) * inv);
            q = min(max(q, 0), 255);
            r |= ((unsigned int)q) << (8*bb);
        }
        u[wd] = r;
    }
    uint4 lo, hi;
    lo.x = __float_as_uint(mn);
    lo.y = __float_as_uint(scale);
    lo.z = u[0]; lo.w = u[1];
    hi.x = u[2]; hi.y = u[3]; hi.z = u[4]; hi.w = u[5];
    lutC[(size_t)i*2]   = lo;
    lutC[(size_t)i*2+1] = hi;
}

// ---------------- AiLUT transform: record-table searchsorted + cube trilerp --
__global__ void __launch_bounds__(256) transform_k(
                            const float* __restrict__ lq, const uint4* __restrict__ lutC,
                            const float* __restrict__ verts, float* __restrict__ out)
{
    int b = blockIdx.x >> 10;
    int blk = blockIdx.x & 1023;
    int tid = threadIdx.x;
    __shared__ float sv[3][DV];
    __shared__ float4 s_int[3][33];
    __shared__ float4 s_edge[3][128];
    if (tid < 99) sv[tid/33][tid%33] = verts[b*99 + tid];
    __syncthreads();
    if (tid < 96) {
        int ch = tid / 32, idx = (tid & 31) + 1;
        float vlo = sv[ch][idx-1], vhi = sv[ch][idx];
        float4 r;
        r.x = vlo;
        r.y = 1.f / (vhi - vlo + 1e-8f);
        r.z = (float)(idx - 1);
        r.w = (idx == 32) ? __int_as_float(0x7f800000) : vhi;
        s_int[ch][idx] = r;
    }
    __syncthreads();
    for (int t = tid; t < 384; t += 256) {
        int ch = t >> 7, e = t & 127;
        float edge = (float)e * (1.f/128.f);
        int idx = 0;
        #pragma unroll 8
        for (int m = 1; m <= 32; m++)
            if (sv[ch][m] <= edge) idx = m;
        s_edge[ch][e] = s_int[ch][min(idx, 31) + 1];
    }
    __syncthreads();

    int n = (blk*256 + tid) * 4;
    const float* lqb = lq + (size_t)b*3*NPIX;
    float4 R  = *(const float4*)(lqb + n);
    float4 G  = *(const float4*)(lqb + NPIX + n);
    float4 Bl = *(const float4*)(lqb + 2*NPIX + n);

    float xr[4] = {R.x, R.y, R.z, R.w};
    float xg[4] = {G.x, G.y, G.z, G.w};
    float xb[4] = {Bl.x, Bl.y, Bl.z, Bl.w};
    float orr[4], org[4], orb[4];

    const uint4* base = lutC + (size_t)b*D3*2;

    #pragma unroll
    for (int px = 0; px < 4; px++) {
        int i0, j0, k0;
        float fr, fg, fb;
        float xs[3] = {xr[px], xg[px], xb[px]};
        #pragma unroll
        for (int ch = 0; ch < 3; ch++) {
            float x = xs[ch];
            int e = min((int)(x * 128.f), 127);
            float4 rec = s_edge[ch][e];
            while (x > rec.w)
                rec = s_int[ch][(int)rec.z + 2];
            float f = fminf((x - rec.x) * rec.y, 1.f);
            int cb = (int)rec.z;
            if (ch == 0) { i0 = cb; fr = f; }
            else if (ch == 1) { j0 = cb; fg = f; }
            else { k0 = cb; fb = f; }
        }

        size_t e0 = (size_t)(i0*D2 + j0*DV + k0)*2;
        uint4 lo4 = base[e0];
        uint4 hi4 = base[e0+1];
        float mn = __uint_as_float(lo4.x);
        float sc = __uint_as_float(lo4.y);
        unsigned int u[6] = {lo4.z, lo4.w, hi4.x, hi4.y, hi4.z, hi4.w};

        #pragma unroll
        for (int ch = 0; ch < 3; ch++) {
            float q[8];
            #pragma unroll
            for (int corner = 0; corner < 8; corner++) {
                int t = corner*3 + ch;
                q[corner] = (float)((u[t >> 2] >> ((t & 3)*8)) & 0xffu);
            }
            float l00 = fmaf(fb, q[1] - q[0], q[0]);
            float l01 = fmaf(fb, q[3] - q[2], q[2]);
            float l10 = fmaf(fb, q[5] - q[4], q[4]);
            float l11 = fmaf(fb, q[7] - q[6], q[6]);
            float h0  = fmaf(fg, l01 - l00, l00);
            float h1  = fmaf(fg, l11 - l10, l10);
            float vq  = fmaf(fr, h1 - h0, h0);
            float v   = fmaf(sc, vq, mn);
            v = fminf(fmaxf(v, 0.f), 1.f);
            if (ch == 0) orr[px] = v; else if (ch == 1) org[px] = v; else orb[px] = v;
        }
    }

    float* ob = out + (size_t)b*3*NPIX + n;
    *(float4*)(ob)          = make_float4(orr[0], orr[1], orr[2], orr[3]);
    *(float4*)(ob + NPIX)   = make_float4(org[0], org[1], org[2], org[3]);
    *(float4*)(ob + 2*NPIX) = make_float4(orb[0], orb[1], orb[2], orb[3]);
}

// ---------------- host launcher ----------------------------------------------
extern "C" void kernel_launch(void* const* d_in, const int* in_sizes, int n_in,
                              void* d_out, int out_size)
{
    const float* lq  = (const float*)d_in[0];
    const float* w1  = (const float*)d_in[1];
    const float* b1  = (const float*)d_in[2];
    const float* g1  = (const float*)d_in[3];
    const float* be1 = (const float*)d_in[4];
    const float* w2  = (const float*)d_in[5];
    const float* b2  = (const float*)d_in[6];
    const float* g2  = (const float*)d_in[7];
    const float* be2 = (const float*)d_in[8];
    const float* w3  = (const float*)d_in[9];
    const float* b3  = (const float*)d_in[10];
    const float* g3  = (const float*)d_in[11];
    const float* be3 = (const float*)d_in[12];
    const float* w4  = (const float*)d_in[13];
    const float* b4  = (const float*)d_in[14];
    const float* g4  = (const float*)d_in[15];
    const float* be4 = (const float*)d_in[16];
    const float* w5  = (const float*)d_in[17];
    const float* b5  = (const float*)d_in[18];
    const float* lw  = (const float*)d_in[19];
    const float* lb  = (const float*)d_in[20];
    const float* bw  = (const float*)d_in[21];
    const float* aw  = (const float*)d_in[22];
    const float* ab  = (const float*)d_in[23];

    float *res, *x1, *x2, *x3, *x4, *pa, *pb, *codes, *stats, *wts, *verts;
    uint4* lutC;
    cudaGetSymbolAddress((void**)&res,   g_resized);
    cudaGetSymbolAddress((void**)&x1,    g_x1);
    cudaGetSymbolAddress((void**)&x2,    g_x2);
    cudaGetSymbolAddress((void**)&x3,    g_x3);
    cudaGetSymbolAddress((void**)&x4,    g_x4);
    cudaGetSymbolAddress((void**)&pa,    g_partA);
    cudaGetSymbolAddress((void**)&pb,    g_partB);
    cudaGetSymbolAddress((void**)&codes, g_codes);
    cudaGetSymbolAddress((void**)&stats, g_stats);
    cudaGetSymbolAddress((void**)&wts,   g_wts);
    cudaGetSymbolAddress((void**)&verts, g_verts);
    cudaGetSymbolAddress((void**)&lutC,  g_lutC);

    float* ss1 = stats;          // 4*16*2  = 128
    float* ss2 = stats + 128;    // 4*32*2  = 256
    float* ss3 = stats + 384;    // 4*64*2  = 512
    float* ss4 = stats + 896;    // 4*128*2 = 1024

    float* out = (float*)d_out;
    const int OFF_W = B*3*NPIX;
    const int OFF_V = OFF_W + B*3;

    resize_k<<<(B*3*256*256 + 255)/256, 256>>>(lq, res, stats);

    conv_k<3, 16, 8, 256, 128, false><<<dim3(64, 2, B), 256>>>(
        res, w1, b1, nullptr, nullptr, nullptr, ss1, x1);

    conv_k<16, 32, 4, 128, 64, true><<<dim3(16, 8, B), 256>>>(
        x1, w2, b2, ss1, g1, be1, ss2, x2);

    // conv3: split-IC partials (grid 8x16x4 = 512 blocks) + finalize
    conv_part_k<32, 64, 4, 64, 32><<<dim3(8, 16, B), 256>>>(
        x2, w3, ss2, g2, be2, pa, pb);
    stats_fin_k<64, 32><<<B*64, 256>>>(pa, pb, b3, x3, ss3);

    // conv4: split-IC partials (grid 2x32x4 = 256 blocks) + finalize
    conv_part_k<64, 128, 4, 32, 16><<<dim3(2, 32, B), 256>>>(
        x3, w4, ss3, g3, be3, pa, pb);
    stats_fin_k<128, 16><<<B*128, 256>>>(pa, pb, b4, x4, ss4);

    // conv5: split-IC partials (grid 64x4 = 256 blocks) + pool finalize
    conv5_part_k<<<dim3(64, B), 256>>>(x4, w5, ss4, g4, be4, pa, pb);
    pool_k<<<128, 256>>>(pa, pb, b5, codes);

    mlp_k<<<B, 256>>>(codes, lw, lb, aw, ab, wts, verts, out + OFF_W, out + OFF_V);

    lutC_k<<<(B*D3 + 255)/256, 256>>>(bw, wts, lutC);

    transform_k<<<B*1024, 256>>>(lq, lutC, verts, out);
}